// round 15
// baseline (speedup 1.0000x reference)
#include <cuda_runtime.h>
#include <cstdint>

#define Wd 512
#define BATCH 16
#define NPIX (Wd * Wd)
#define NTOT (BATCH * NPIX)
#define PADW 520
#define PADH 516
#define PADN (PADW * PADH)
#define INV_CELL 2.56f  /* 1 / (200/512) */
#define ROWS_PB 4
#define FILL_BYTES ((ROWS_PB + 4) * PADW * 4)
#define RAIN_BYTES (ROWS_PB * Wd * 4)

// Padded tm1 (= terrain - 1) buffers, zero borders.
// Logical (i,j) lives at pad[(i+2)*PADW + (j+4)].
__device__ __align__(16) float g_padA[BATCH * PADN];
__device__ __align__(16) float g_padB[BATCH * PADN];
__device__ __align__(16) float2 g_sw[NTOT];     // x=sed y=wat
__device__ __align__(16) float g_vel[NTOT];
__device__ float g_par[8];

__device__ __forceinline__ void pdl_wait() {
    asm volatile("griddepcontrol.wait;" ::: "memory");
}
__device__ __forceinline__ void pdl_launch_dependents() {
    asm volatile("griddepcontrol.launch_dependents;" ::: "memory");
}

__global__ void init_kernel(const float* __restrict__ in,
                            const float* rr, const float* ev, const float* mh,
                            const float* he, const float* gr, const float* kc,
                            const float* di, const float* de) {
    if (blockIdx.x == 0 && threadIdx.x == 0) {
        g_par[0] = fmaxf(*rr, 0.0f);            // relu(rain_rate)
        g_par[1] = *he;                         // height_epsilon
        g_par[2] = *mh;                         // min_height_delta
        g_par[3] = fmaxf(*kc, 0.0f) * INV_CELL; // relu(kc)/CELL_W
        g_par[4] = *di;                         // dissolving_rate
        g_par[5] = *de;                         // deposition_rate
        g_par[6] = 1.0f - fmaxf(*ev, 0.0f);     // 1 - relu(evap)
        g_par[7] = fmaxf(*gr, 0.0f) * INV_CELL; // relu(g)/CELL_W
    }
    int row = blockIdx.x;            // 0 .. BATCH*PADH-1
    int b = row / PADH;
    int pi = row - b * PADH;
    int pj = threadIdx.x;            // 0 .. 519
    int pidx = b * PADN + pi * PADW + pj;
    if (pi >= 2 && pi < 2 + Wd && pj >= 4 && pj < 4 + Wd) {
        int i = pi - 2, j = pj - 4;
        int cidx = b * NPIX + i * Wd + j;
        float t0 = (1.0f - in[cidx]) * 0.5f;
        g_padA[pidx] = t0 - 1.0f;            // reference's tm1, exactly
    } else {
        g_padA[pidx] = 0.0f;
        g_padB[pidx] = 0.0f;
    }
    pdl_launch_dependents();
}

__device__ __forceinline__ uint32_t smem_u32(const void* p) {
    uint32_t a;
    asm("{ .reg .u64 t; cvta.to.shared.u64 t, %1; cvt.u32.u64 %0, t; }"
        : "=r"(a) : "l"(p));
    return a;
}

// Staging prologue: t0 owns the mbarrier end-to-end.
__device__ __forceinline__ void stage_tiles(const float* pin, const float* rain,
                                            int b, int i0, int t,
                                            float* sm, float* smr, uint32_t mb) {
    if (t == 0) {
        asm volatile("mbarrier.init.shared.b64 [%0], 1;" :: "r"(mb) : "memory");
        asm volatile("mbarrier.arrive.expect_tx.shared.b64 _, [%0], %1;"
                     :: "r"(mb), "r"(FILL_BYTES + RAIN_BYTES) : "memory");
        const float* src = pin + (size_t)b * PADN + (size_t)i0 * PADW;
        asm volatile(
            "cp.async.bulk.shared::cluster.global.mbarrier::complete_tx::bytes "
            "[%0], [%1], %2, [%3];"
            :: "r"(smem_u32(sm)), "l"(src), "r"(FILL_BYTES), "r"(mb) : "memory");
        const float* rsrc = rain + (size_t)i0 * Wd;
        asm volatile(
            "cp.async.bulk.shared::cluster.global.mbarrier::complete_tx::bytes "
            "[%0], [%1], %2, [%3];"
            :: "r"(smem_u32(smr)), "l"(rsrc), "r"(RAIN_BYTES), "r"(mb) : "memory");
    }
}

__device__ __forceinline__ void wait_tiles(int t, uint32_t mb) {
    if (t == 0) {
        uint32_t done = 0;
        while (!done) {
            asm volatile(
                "{ .reg .pred p; mbarrier.try_wait.parity.shared.b64 p, [%1], 0, 0x989680; "
                "selp.u32 %0, 1, 0, p; }"
                : "=r"(done) : "r"(mb) : "memory");
        }
    }
    __syncthreads();
}

// Gradient + bilinear gather (tm1-space), boundary checks pruned at compile time:
// jj==0 only possible when KK==0; jj==Wd-1 only when KK==7.
template <int KK>
__device__ __forceinline__ float grad_gather(const float* sm, const float* smc,
                                             int jj, int i0,
                                             bool interior_i, float rowsc,
                                             float fi, float& fdy_out) {
    float tcm = smc[jj];

    float dx;
    if (interior_i) {
        dx = 0.5f * (smc[jj + PADW] - smc[jj - PADW]);
    } else {
        float tcf = tcm + 1.0f;
        dx = 0.5f * (tcf * rowsc - tcf);
    }

    float dy;
    if (KK == 0 && jj == 0) {
        float tcf = tcm + 1.0f;
        dy = 0.5f * (tcf * 1.1f - tcf);
    } else if (KK == 7 && jj == Wd - 1) {
        float tcf = tcm + 1.0f;
        dy = 0.5f * (tcf * 0.9f - tcf);
    } else {
        dy = 0.5f * (smc[jj + 1] - smc[jj - 1]);
    }

    float rinv = rsqrtf(dx * dx + dy * dy + 1e-11f);
    float fdx = dx * rinv;
    float fdy = dy * rinv;
    fdy_out = fdy;

    float fx = (float)jj - fdx;
    float fy = fi - fdy;
    float x0 = floorf(fx), y0 = floorf(fy);
    float wx = fx - x0, wy = fy - y0;
    int ix = (int)x0;
    int iy = (int)y0;

    const float* g = sm + (iy - i0 + 2) * PADW + (ix + 4);
    float g00 = g[0];
    float g10 = g[1];
    float g01 = g[PADW];
    float g11 = g[PADW + 1];
    float nbm = (1.0f - wy) * ((1.0f - wx) * g00 + wx * g10)
              + wy          * ((1.0f - wx) * g01 + wx * g11);

    return tcm - nbm;
}

template <int KK>
__device__ __forceinline__ float disp_fac(float fdy, int jj) {
    float ad = fabsf(fdy);
    float r2v = fmaxf(1.0f - ad, 0.0f);
    float fac = ad + r2v;
    if (KK == 0 && jj == 0)        fac = fmaxf(-fdy, 0.0f) + r2v;  // t3 zeroed at col 0
    if (KK == 7 && jj == Wd - 1)   fac = r2v + fmaxf(fdy, 0.0f);   // t1 zeroed at col W-1
    return fac;
}

// ---------------- step 0 (s=v=0 -> dep==0; stores wat only + vel) ----------------
template <int KK>
__device__ __forceinline__ void step0_px(const float* sm, const float* smc,
                                         const float* smrr, int q, int i0,
                                         bool interior_i, float rowsc, float fi,
                                         float4 pA, float4 pB, int cbase) {
    int jj = q + (KK << 6);
    float fdy;
    float hd = grad_gather<KK>(sm, smc, jj, i0, interior_i, rowsc, fi, fdy);
    float w = pA.x * smrr[jj];
    float fac = disp_fac<KK>(fdy, jj);
    int cidx = cbase + jj;
    g_sw[cidx].y = (fac * w) * pB.z;   // sed slot unread by step 1 (SED0)
    g_vel[cidx] = pB.w * hd;
}

__global__ void __launch_bounds__(256)
step0_kernel(const float* __restrict__ pin, const float* __restrict__ rain) {
    __shared__ __align__(16) float sm[(ROWS_PB + 4) * PADW];
    __shared__ __align__(16) float smr[ROWS_PB * Wd];
    __shared__ __align__(8) unsigned long long mbar;

    int blk = blockIdx.x;
    int b = blk >> 7;
    int i0 = (blk & 127) << 2;
    int t = threadIdx.x;
    int r = t >> 6;
    int q = t & 63;
    int i = i0 + r;

    uint32_t mb = smem_u32(&mbar);
    pdl_wait();
    stage_tiles(pin, rain, b, i0, t, sm, smr, mb);
    wait_tiles(t, mb);

    const float4* parv = reinterpret_cast<const float4*>(g_par);
    float4 pA = parv[0];
    float4 pB = parv[1];

    const float* smc = sm + (r + 2) * PADW + 4;
    const float* smrr = smr + r * Wd;
    bool interior_i = (i > 0) && (i < Wd - 1);
    float rowsc = (i == 0) ? 1.1f : 0.9f;
    float fi = (float)i;
    int cbase = b * NPIX + i * Wd;

    step0_px<0>(sm, smc, smrr, q, i0, interior_i, rowsc, fi, pA, pB, cbase);
    step0_px<1>(sm, smc, smrr, q, i0, interior_i, rowsc, fi, pA, pB, cbase);
    step0_px<2>(sm, smc, smrr, q, i0, interior_i, rowsc, fi, pA, pB, cbase);
    step0_px<3>(sm, smc, smrr, q, i0, interior_i, rowsc, fi, pA, pB, cbase);
    step0_px<4>(sm, smc, smrr, q, i0, interior_i, rowsc, fi, pA, pB, cbase);
    step0_px<5>(sm, smc, smrr, q, i0, interior_i, rowsc, fi, pA, pB, cbase);
    step0_px<6>(sm, smc, smrr, q, i0, interior_i, rowsc, fi, pA, pB, cbase);
    step0_px<7>(sm, smc, smrr, q, i0, interior_i, rowsc, fi, pA, pB, cbase);
    pdl_launch_dependents();
}

// ---------------- generic step ----------------
template <int KK, bool LAST, bool SED0>
__device__ __forceinline__ void step_px(const float* sm, const float* smc,
                                        const float* smrr, int q, int i0,
                                        bool interior_i, float rowsc, float fi,
                                        float4 pA, float4 pB,
                                        float s, float w_in, float v,
                                        int cbase, float* porow, float* outp) {
    int jj = q + (KK << 6);
    float fdy;
    float hd = grad_gather<KK>(sm, smc, jj, i0, interior_i, rowsc, fi, fdy);
    float nhd = (hd > pA.y) ? fmaxf(hd, pA.z) : 0.0f;

    float w = w_in + pA.x * smrr[jj];

    float scap = nhd * pA.w * v * w;
    float first = SED0 ? 0.0f : fminf(fmaxf(-hd, 0.0f), s);   // s==0 -> min(relu,0)==0 exact
    float sdiff = (SED0 ? 0.0f : s) - scap;
    float third = (hd < 0.0f) ? 0.0f
                : (fmaxf(sdiff * pB.y, 0.0f) - fmaxf(-sdiff * pB.x, 0.0f));
    float dep = fmaxf(-fmaxf(hd, 0.0f), first + third);

    float t2m = smc[jj] + dep;    // = new terrain - 1

    if (LAST) {
        // Post-step-9 state dead: no displacement, no state stores.
        outp[cbase + jj] = fmaxf(-2.0f * t2m, 0.0f) - 1.0f;
    } else {
        float s2 = (SED0 ? 0.0f : s) - dep;
        float fac = disp_fac<KK>(fdy, jj);
        int cidx = cbase + jj;
        g_sw[cidx] = make_float2(fac * s2, (fac * w) * pB.z);
        g_vel[cidx] = pB.w * hd;
        porow[jj] = t2m;
    }
}

template <bool LAST, bool SED0>
__global__ void __launch_bounds__(256)
step_kernel(const float* __restrict__ pin, float* __restrict__ pout,
            const float* __restrict__ rain, float* __restrict__ outp) {
    __shared__ __align__(16) float sm[(ROWS_PB + 4) * PADW];
    __shared__ __align__(16) float smr[ROWS_PB * Wd];
    __shared__ __align__(8) unsigned long long mbar;

    int blk = blockIdx.x;
    int b = blk >> 7;
    int i0 = (blk & 127) << 2;
    int t = threadIdx.x;
    int r = t >> 6;
    int q = t & 63;
    int i = i0 + r;

    uint32_t mb = smem_u32(&mbar);
    pdl_wait();
    stage_tiles(pin, rain, b, i0, t, sm, smr, mb);

    int cbase = b * NPIX + i * Wd;

    const float4* parv = reinterpret_cast<const float4*>(g_par);
    float4 pA = parv[0];  // x=rain_rate' y=heps z=minhd w=kc'
    float4 pB = parv[1];  // x=dis y=dep z=evap' w=grav'

    // ---- first half's state loads, front-batched to overlap the TMA fills ----
    float s_[4], w_[4], v_[4];
#pragma unroll
    for (int k = 0; k < 4; ++k) {
        int jj = q + (k << 6);
        if (SED0) {
            s_[k] = 0.0f;
            w_[k] = g_sw[cbase + jj].y;
        } else {
            float2 sw = g_sw[cbase + jj];
            s_[k] = sw.x;
            w_[k] = sw.y;
        }
        v_[k] = g_vel[cbase + jj];
    }

    wait_tiles(t, mb);

    const float* smc = sm + (r + 2) * PADW + 4;
    const float* smrr = smr + r * Wd;
    bool interior_i = (i > 0) && (i < Wd - 1);
    float rowsc = (i == 0) ? 1.1f : 0.9f;
    float fi = (float)i;
    float* porow = pout + (size_t)b * PADN + (size_t)(i + 2) * PADW + 4;

    step_px<0, LAST, SED0>(sm, smc, smrr, q, i0, interior_i, rowsc, fi, pA, pB,
                           s_[0], w_[0], v_[0], cbase, porow, outp);
    step_px<1, LAST, SED0>(sm, smc, smrr, q, i0, interior_i, rowsc, fi, pA, pB,
                           s_[1], w_[1], v_[1], cbase, porow, outp);
    step_px<2, LAST, SED0>(sm, smc, smrr, q, i0, interior_i, rowsc, fi, pA, pB,
                           s_[2], w_[2], v_[2], cbase, porow, outp);
    step_px<3, LAST, SED0>(sm, smc, smrr, q, i0, interior_i, rowsc, fi, pA, pB,
                           s_[3], w_[3], v_[3], cbase, porow, outp);

    // second half's state loads, front-batched
#pragma unroll
    for (int k = 0; k < 4; ++k) {
        int jj = q + ((k + 4) << 6);
        if (SED0) {
            s_[k] = 0.0f;
            w_[k] = g_sw[cbase + jj].y;
        } else {
            float2 sw = g_sw[cbase + jj];
            s_[k] = sw.x;
            w_[k] = sw.y;
        }
        v_[k] = g_vel[cbase + jj];
    }

    step_px<4, LAST, SED0>(sm, smc, smrr, q, i0, interior_i, rowsc, fi, pA, pB,
                           s_[0], w_[0], v_[0], cbase, porow, outp);
    step_px<5, LAST, SED0>(sm, smc, smrr, q, i0, interior_i, rowsc, fi, pA, pB,
                           s_[1], w_[1], v_[1], cbase, porow, outp);
    step_px<6, LAST, SED0>(sm, smc, smrr, q, i0, interior_i, rowsc, fi, pA, pB,
                           s_[2], w_[2], v_[2], cbase, porow, outp);
    step_px<7, LAST, SED0>(sm, smc, smrr, q, i0, interior_i, rowsc, fi, pA, pB,
                           s_[3], w_[3], v_[3], cbase, porow, outp);

    pdl_launch_dependents();
}

template <typename F, typename... Args>
static inline void launch_pdl(F fn, dim3 g, dim3 b, Args... args) {
    cudaLaunchConfig_t cfg = {};
    cfg.gridDim = g;
    cfg.blockDim = b;
    cfg.dynamicSmemBytes = 0;
    cfg.stream = 0;
    cudaLaunchAttribute at[1];
    at[0].id = cudaLaunchAttributeProgrammaticStreamSerialization;
    at[0].val.programmaticStreamSerializationAllowed = 1;
    cfg.attrs = at;
    cfg.numAttrs = 1;
    cudaLaunchKernelEx(&cfg, fn, args...);
}

extern "C" void kernel_launch(void* const* d_in, const int* in_sizes, int n_in,
                              void* d_out, int out_size) {
    const float* input     = (const float*)d_in[0];
    const float* rainall   = (const float*)d_in[1];
    // d_in[2] (random_gradient) provably unused: factor == relu(1e-10 - mag) == 0 in fp32.
    const float* rain_rate = (const float*)d_in[3];
    const float* evap      = (const float*)d_in[4];
    const float* minhd     = (const float*)d_in[5];
    const float* heps      = (const float*)d_in[6];
    const float* grav      = (const float*)d_in[7];
    const float* kc        = (const float*)d_in[8];
    const float* dis       = (const float*)d_in[9];
    const float* depr      = (const float*)d_in[10];
    float* out = (float*)d_out;

    float *pA, *pB;
    cudaGetSymbolAddress((void**)&pA, g_padA);
    cudaGetSymbolAddress((void**)&pB, g_padB);

    init_kernel<<<BATCH * PADH, PADW>>>(input, rain_rate, evap, minhd, heps,
                                        grav, kc, dis, depr);

    // Step 0: dep == 0 exactly (s=v=0) -> terrain unchanged; only wat/vel produced.
    launch_pdl(step0_kernel, dim3(BATCH * 128), dim3(256),
               (const float*)pA, rainall);

    // Step 1: sed provably zero -> SED0 instantiation (no sed load, folded math).
    launch_pdl(step_kernel<false, true>, dim3(BATCH * 128), dim3(256),
               (const float*)pA, pB, rainall + (size_t)1 * NPIX, out);

    // Steps 2..9: ping-pong terrain.
    for (int it = 2; it < 10; ++it) {
        const float* pin = (it & 1) ? pA : pB;
        float* pout      = (it & 1) ? pB : pA;
        const float* rain = rainall + (size_t)it * NPIX;
        if (it == 9) {
            launch_pdl(step_kernel<true, false>, dim3(BATCH * 128), dim3(256),
                       pin, pout, rain, out);
        } else {
            launch_pdl(step_kernel<false, false>, dim3(BATCH * 128), dim3(256),
                       pin, pout, rain, out);
        }
    }
}

// round 16
// speedup vs baseline: 1.0795x; 1.0795x over previous
#include <cuda_runtime.h>
#include <cstdint>

#define Wd 512
#define BATCH 16
#define NPIX (Wd * Wd)
#define NTOT (BATCH * NPIX)
#define PADW 520
#define PADH 516
#define PADN (PADW * PADH)
#define INV_CELL 2.56f  /* 1 / (200/512) */
#define ROWS_PB 4
#define FILL_BYTES ((ROWS_PB + 4) * PADW * 4)
#define RAIN_BYTES (ROWS_PB * Wd * 4)

// Padded tm1 (= terrain - 1) buffers, zero borders.
// Logical (i,j) lives at pad[(i+2)*PADW + (j+4)].
__device__ __align__(16) float g_padA[BATCH * PADN];
__device__ __align__(16) float g_padB[BATCH * PADN];
__device__ __align__(16) float2 g_sw[NTOT];     // x=sed y=wat
__device__ __align__(16) float g_vel[NTOT];
__device__ float g_par[8];

__device__ __forceinline__ void pdl_wait() {
    asm volatile("griddepcontrol.wait;" ::: "memory");
}
__device__ __forceinline__ void pdl_launch_dependents() {
    asm volatile("griddepcontrol.launch_dependents;" ::: "memory");
}

__global__ void init_kernel(const float* __restrict__ in,
                            const float* rr, const float* ev, const float* mh,
                            const float* he, const float* gr, const float* kc,
                            const float* di, const float* de) {
    if (blockIdx.x == 0 && threadIdx.x == 0) {
        g_par[0] = fmaxf(*rr, 0.0f);            // relu(rain_rate)
        g_par[1] = *he;                         // height_epsilon
        g_par[2] = *mh;                         // min_height_delta
        g_par[3] = fmaxf(*kc, 0.0f) * INV_CELL; // relu(kc)/CELL_W
        g_par[4] = *di;                         // dissolving_rate
        g_par[5] = *de;                         // deposition_rate
        g_par[6] = 1.0f - fmaxf(*ev, 0.0f);     // 1 - relu(evap)
        g_par[7] = fmaxf(*gr, 0.0f) * INV_CELL; // relu(g)/CELL_W
    }
    int row = blockIdx.x;            // 0 .. BATCH*PADH-1
    int b = row / PADH;
    int pi = row - b * PADH;
    int pj = threadIdx.x;            // 0 .. 519
    int pidx = b * PADN + pi * PADW + pj;
    if (pi >= 2 && pi < 2 + Wd && pj >= 4 && pj < 4 + Wd) {
        int i = pi - 2, j = pj - 4;
        int cidx = b * NPIX + i * Wd + j;
        float t0 = (1.0f - in[cidx]) * 0.5f;
        g_padA[pidx] = t0 - 1.0f;            // reference's tm1, exactly
    } else {
        g_padA[pidx] = 0.0f;
        g_padB[pidx] = 0.0f;
    }
    pdl_launch_dependents();
}

__device__ __forceinline__ uint32_t smem_u32(const void* p) {
    uint32_t a;
    asm("{ .reg .u64 t; cvta.to.shared.u64 t, %1; cvt.u32.u64 %0, t; }"
        : "=r"(a) : "l"(p));
    return a;
}

// t0 owns the mbarrier end-to-end; wait_tiles' __syncthreads is the release.
__device__ __forceinline__ void tma_copy(float* dst, const float* src,
                                         uint32_t bytes, uint32_t mb) {
    asm volatile(
        "cp.async.bulk.shared::cluster.global.mbarrier::complete_tx::bytes "
        "[%0], [%1], %2, [%3];"
        :: "r"(smem_u32(dst)), "l"(src), "r"(bytes), "r"(mb) : "memory");
}

__device__ __forceinline__ void wait_tiles(int t, uint32_t mb) {
    if (t == 0) {
        uint32_t done = 0;
        while (!done) {
            asm volatile(
                "{ .reg .pred p; mbarrier.try_wait.parity.shared.b64 p, [%1], 0, 0x989680; "
                "selp.u32 %0, 1, 0, p; }"
                : "=r"(done) : "r"(mb) : "memory");
        }
    }
    __syncthreads();
}

// Gradient + bilinear gather (tm1-space). Returns hd; writes fdy.
__device__ __forceinline__ float grad_gather(const float* sm, const float* smc,
                                             int jj, int i0,
                                             bool interior_i, float rowsc,
                                             float fi, float& fdy_out) {
    float tcm = smc[jj];

    float dx;
    if (interior_i) {
        dx = 0.5f * (smc[jj + PADW] - smc[jj - PADW]);
    } else {
        float tcf = tcm + 1.0f;
        dx = 0.5f * (tcf * rowsc - tcf);
    }

    float dy;
    if (jj == 0) {
        float tcf = tcm + 1.0f;
        dy = 0.5f * (tcf * 1.1f - tcf);
    } else if (jj == Wd - 1) {
        float tcf = tcm + 1.0f;
        dy = 0.5f * (tcf * 0.9f - tcf);
    } else {
        dy = 0.5f * (smc[jj + 1] - smc[jj - 1]);
    }

    float rinv = rsqrtf(dx * dx + dy * dy + 1e-11f);
    float fdx = dx * rinv;
    float fdy = dy * rinv;
    fdy_out = fdy;

    float fx = (float)jj - fdx;
    float fy = fi - fdy;
    float x0 = floorf(fx), y0 = floorf(fy);
    float wx = fx - x0, wy = fy - y0;
    int ix = (int)x0;
    int iy = (int)y0;

    const float* g = sm + (iy - i0 + 2) * PADW + (ix + 4);
    float g00 = g[0];
    float g10 = g[1];
    float g01 = g[PADW];
    float g11 = g[PADW + 1];
    float nbm = (1.0f - wy) * ((1.0f - wx) * g00 + wx * g10)
              + wy          * ((1.0f - wx) * g01 + wx * g11);

    return tcm - nbm;
}

__device__ __forceinline__ float disp_fac(float fdy, int jj) {
    float ad = fabsf(fdy);
    float r2v = fmaxf(1.0f - ad, 0.0f);
    float fac = ad + r2v;
    if (jj == 0)        fac = fmaxf(-fdy, 0.0f) + r2v;  // t3 zeroed at col 0
    if (jj == Wd - 1)   fac = r2v + fmaxf(fdy, 0.0f);   // t1 zeroed at col W-1
    return fac;
}

// ---------------- fused steps 0+1 ----------------
// Step 0: s=v=0 -> dep==0 exactly -> terrain unchanged -> step 1 sees the SAME
// terrain, hence the SAME gradient/gather/hd/fac. Step-0 wat/vel live only in
// registers; step-1 uses the s==0 folds (first=0, sdiff=-scap, s2=-dep).
__global__ void __launch_bounds__(256)
step01_kernel(const float* __restrict__ pin, float* __restrict__ pout,
              const float* __restrict__ rain0, const float* __restrict__ rain1) {
    __shared__ __align__(16) float sm[(ROWS_PB + 4) * PADW];
    __shared__ __align__(16) float smr0[ROWS_PB * Wd];
    __shared__ __align__(16) float smr1[ROWS_PB * Wd];
    __shared__ __align__(8) unsigned long long mbar;

    int blk = blockIdx.x;
    int b = blk >> 7;
    int i0 = (blk & 127) << 2;
    int t = threadIdx.x;
    int r = t >> 6;
    int q = t & 63;
    int i = i0 + r;

    uint32_t mb = smem_u32(&mbar);
    pdl_wait();
    if (t == 0) {
        asm volatile("mbarrier.init.shared.b64 [%0], 1;" :: "r"(mb) : "memory");
        asm volatile("mbarrier.arrive.expect_tx.shared.b64 _, [%0], %1;"
                     :: "r"(mb), "r"(FILL_BYTES + 2 * RAIN_BYTES) : "memory");
        tma_copy(sm,   pin + (size_t)b * PADN + (size_t)i0 * PADW, FILL_BYTES, mb);
        tma_copy(smr0, rain0 + (size_t)i0 * Wd, RAIN_BYTES, mb);
        tma_copy(smr1, rain1 + (size_t)i0 * Wd, RAIN_BYTES, mb);
    }
    wait_tiles(t, mb);

    const float4* parv = reinterpret_cast<const float4*>(g_par);
    float4 pA = parv[0];  // x=rain_rate' y=heps z=minhd w=kc'
    float4 pB = parv[1];  // x=dis y=dep z=evap' w=grav'

    const float* smc = sm + (r + 2) * PADW + 4;
    const float* smrr0 = smr0 + r * Wd;
    const float* smrr1 = smr1 + r * Wd;
    bool interior_i = (i > 0) && (i < Wd - 1);
    float rowsc = (i == 0) ? 1.1f : 0.9f;
    float fi = (float)i;
    int cbase = b * NPIX + i * Wd;
    float* porow = pout + (size_t)b * PADN + (size_t)(i + 2) * PADW + 4;

#pragma unroll
    for (int k = 0; k < 8; ++k) {
        int jj = q + (k << 6);

        float fdy;
        float hd = grad_gather(sm, smc, jj, i0, interior_i, rowsc, fi, fdy);
        float fac = disp_fac(fdy, jj);

        // --- step 0 (register-resident) ---
        float w0 = pA.x * smrr0[jj];
        float wat0 = (fac * w0) * pB.z;
        float vel0 = pB.w * hd;

        // --- step 1 (s == 0 folds, exact) ---
        float nhd = (hd > pA.y) ? fmaxf(hd, pA.z) : 0.0f;
        float w = wat0 + pA.x * smrr1[jj];
        float scap = nhd * pA.w * vel0 * w;
        float sdiff = 0.0f - scap;
        float third = (hd < 0.0f) ? 0.0f
                    : (fmaxf(sdiff * pB.y, 0.0f) - fmaxf(-sdiff * pB.x, 0.0f));
        float dep = fmaxf(-fmaxf(hd, 0.0f), 0.0f + third);

        float s2 = 0.0f - dep;
        float t2m = smc[jj] + dep;

        int cidx = cbase + jj;
        g_sw[cidx] = make_float2(fac * s2, (fac * w) * pB.z);
        g_vel[cidx] = pB.w * hd;
        porow[jj] = t2m;
    }
    pdl_launch_dependents();
}

// ---------------- generic step (R14 version) ----------------
template <bool LAST>
__global__ void __launch_bounds__(256)
step_kernel(const float* __restrict__ pin, float* __restrict__ pout,
            const float* __restrict__ rain, float* __restrict__ outp) {
    __shared__ __align__(16) float sm[(ROWS_PB + 4) * PADW];
    __shared__ __align__(16) float smr[ROWS_PB * Wd];
    __shared__ __align__(8) unsigned long long mbar;

    int blk = blockIdx.x;
    int b = blk >> 7;
    int i0 = (blk & 127) << 2;
    int t = threadIdx.x;
    int r = t >> 6;
    int q = t & 63;
    int i = i0 + r;

    uint32_t mb = smem_u32(&mbar);
    pdl_wait();
    if (t == 0) {
        asm volatile("mbarrier.init.shared.b64 [%0], 1;" :: "r"(mb) : "memory");
        asm volatile("mbarrier.arrive.expect_tx.shared.b64 _, [%0], %1;"
                     :: "r"(mb), "r"(FILL_BYTES + RAIN_BYTES) : "memory");
        tma_copy(sm,  pin + (size_t)b * PADN + (size_t)i0 * PADW, FILL_BYTES, mb);
        tma_copy(smr, rain + (size_t)i0 * Wd, RAIN_BYTES, mb);
    }

    int cbase = b * NPIX + i * Wd;

    const float4* parv = reinterpret_cast<const float4*>(g_par);
    float4 pA = parv[0];  // x=rain_rate' y=heps z=minhd w=kc'
    float4 pB = parv[1];  // x=dis y=dep z=evap' w=grav'

    // ---- first half's state loads, front-batched to overlap the TMA fills ----
    float2 sw_[4];
    float v_[4];
#pragma unroll
    for (int k = 0; k < 4; ++k) {
        int jj = q + (k << 6);
        sw_[k] = g_sw[cbase + jj];
        v_[k]  = g_vel[cbase + jj];
    }

    wait_tiles(t, mb);

    const float* smc = sm + (r + 2) * PADW + 4;
    const float* smrr = smr + r * Wd;
    bool interior_i = (i > 0) && (i < Wd - 1);
    float rowsc = (i == 0) ? 1.1f : 0.9f;
    float fi = (float)i;
    float* porow = pout + (size_t)b * PADN + (size_t)(i + 2) * PADW + 4;

#pragma unroll
    for (int half = 0; half < 2; ++half) {
        if (half == 1) {
#pragma unroll
            for (int k = 0; k < 4; ++k) {
                int jj = q + ((k + 4) << 6);
                sw_[k] = g_sw[cbase + jj];
                v_[k]  = g_vel[cbase + jj];
            }
        }

#pragma unroll
        for (int k = 0; k < 4; ++k) {
            int jj = q + ((half * 4 + k) << 6);

            float fdy;
            float hd = grad_gather(sm, smc, jj, i0, interior_i, rowsc, fi, fdy);
            float nhd = (hd > pA.y) ? fmaxf(hd, pA.z) : 0.0f;

            float s = sw_[k].x;
            float w = sw_[k].y + pA.x * smrr[jj];

            float scap = nhd * pA.w * v_[k] * w;
            float first = fminf(fmaxf(-hd, 0.0f), s);
            float sdiff = s - scap;
            float third = (hd < 0.0f) ? 0.0f
                        : (fmaxf(sdiff * pB.y, 0.0f) - fmaxf(-sdiff * pB.x, 0.0f));
            float dep = fmaxf(-fmaxf(hd, 0.0f), first + third);

            float t2m = smc[jj] + dep;    // = new terrain - 1

            if (LAST) {
                // Post-step-9 state dead: no displacement, no state stores.
                outp[cbase + jj] = fmaxf(-2.0f * t2m, 0.0f) - 1.0f;
            } else {
                float s2 = s - dep;
                float fac = disp_fac(fdy, jj);
                int cidx = cbase + jj;
                g_sw[cidx] = make_float2(fac * s2, (fac * w) * pB.z);
                g_vel[cidx] = pB.w * hd;
                porow[jj] = t2m;
            }
        }
    }
    pdl_launch_dependents();
}

template <typename F, typename... Args>
static inline void launch_pdl(F fn, dim3 g, dim3 b, Args... args) {
    cudaLaunchConfig_t cfg = {};
    cfg.gridDim = g;
    cfg.blockDim = b;
    cfg.dynamicSmemBytes = 0;
    cfg.stream = 0;
    cudaLaunchAttribute at[1];
    at[0].id = cudaLaunchAttributeProgrammaticStreamSerialization;
    at[0].val.programmaticStreamSerializationAllowed = 1;
    cfg.attrs = at;
    cfg.numAttrs = 1;
    cudaLaunchKernelEx(&cfg, fn, args...);
}

extern "C" void kernel_launch(void* const* d_in, const int* in_sizes, int n_in,
                              void* d_out, int out_size) {
    const float* input     = (const float*)d_in[0];
    const float* rainall   = (const float*)d_in[1];
    // d_in[2] (random_gradient) provably unused: factor == relu(1e-10 - mag) == 0 in fp32.
    const float* rain_rate = (const float*)d_in[3];
    const float* evap      = (const float*)d_in[4];
    const float* minhd     = (const float*)d_in[5];
    const float* heps      = (const float*)d_in[6];
    const float* grav      = (const float*)d_in[7];
    const float* kc        = (const float*)d_in[8];
    const float* dis       = (const float*)d_in[9];
    const float* depr      = (const float*)d_in[10];
    float* out = (float*)d_out;

    float *pA, *pB;
    cudaGetSymbolAddress((void**)&pA, g_padA);
    cudaGetSymbolAddress((void**)&pB, g_padB);

    init_kernel<<<BATCH * PADH, PADW>>>(input, rain_rate, evap, minhd, heps,
                                        grav, kc, dis, depr);

    // Fused steps 0+1: terrain unchanged by step 0, so one staging + one
    // gradient serves both; step-0 wat/vel stay in registers.
    launch_pdl(step01_kernel, dim3(BATCH * 128), dim3(256),
               (const float*)pA, pB, rainall, rainall + (size_t)NPIX);

    // Steps 2..9: ping-pong terrain (step 2 reads pB).
    for (int it = 2; it < 10; ++it) {
        const float* pin = (it & 1) ? pA : pB;
        float* pout      = (it & 1) ? pB : pA;
        const float* rain = rainall + (size_t)it * NPIX;
        if (it == 9) {
            launch_pdl(step_kernel<true>, dim3(BATCH * 128), dim3(256),
                       pin, pout, rain, out);
        } else {
            launch_pdl(step_kernel<false>, dim3(BATCH * 128), dim3(256),
                       pin, pout, rain, out);
        }
    }
}

// round 17
// speedup vs baseline: 1.1023x; 1.0211x over previous
#include <cuda_runtime.h>
#include <cstdint>

#define Wd 512
#define BATCH 16
#define NPIX (Wd * Wd)
#define NTOT (BATCH * NPIX)
#define PADW 520
#define PADH 516
#define PADN (PADW * PADH)
#define INV_CELL 2.56f  /* 1 / (200/512) */
#define ROWS_PB 4
#define FILL_BYTES ((ROWS_PB + 4) * PADW * 4)
#define RAIN_BYTES (ROWS_PB * Wd * 4)

// Padded tm1 (= terrain - 1) ping-pong buffers, zero borders.
// Logical (i,j) lives at pad[(i+2)*PADW + (j+4)].
__device__ __align__(16) float g_padA[BATCH * PADN];
__device__ __align__(16) float g_padB[BATCH * PADN];
__device__ __align__(16) float2 g_sw[NTOT];     // x=sed y=wat
__device__ __align__(16) float g_vel[NTOT];
__device__ float g_par[8];

__device__ __forceinline__ void pdl_wait() {
    asm volatile("griddepcontrol.wait;" ::: "memory");
}
__device__ __forceinline__ void pdl_launch_dependents() {
    asm volatile("griddepcontrol.launch_dependents;" ::: "memory");
}

// init: params + zero the borders of BOTH pad buffers (interiors are always
// written by a step before being read). No input read, no interior write.
__global__ void init_kernel(const float* rr, const float* ev, const float* mh,
                            const float* he, const float* gr, const float* kc,
                            const float* di, const float* de) {
    if (blockIdx.x == 0 && threadIdx.x == 0) {
        g_par[0] = fmaxf(*rr, 0.0f);            // relu(rain_rate)
        g_par[1] = *he;                         // height_epsilon
        g_par[2] = *mh;                         // min_height_delta
        g_par[3] = fmaxf(*kc, 0.0f) * INV_CELL; // relu(kc)/CELL_W
        g_par[4] = *di;                         // dissolving_rate
        g_par[5] = *de;                         // deposition_rate
        g_par[6] = 1.0f - fmaxf(*ev, 0.0f);     // 1 - relu(evap)
        g_par[7] = fmaxf(*gr, 0.0f) * INV_CELL; // relu(g)/CELL_W
    }
    int row = blockIdx.x;            // 0 .. BATCH*PADH-1
    int b = row / PADH;
    int pi = row - b * PADH;
    int pj = threadIdx.x;            // 0 .. 519
    bool border = !(pi >= 2 && pi < 2 + Wd && pj >= 4 && pj < 4 + Wd);
    if (border) {
        int pidx = b * PADN + pi * PADW + pj;
        g_padA[pidx] = 0.0f;
        g_padB[pidx] = 0.0f;
    }
    pdl_launch_dependents();
}

__device__ __forceinline__ uint32_t smem_u32(const void* p) {
    uint32_t a;
    asm("{ .reg .u64 t; cvta.to.shared.u64 t, %1; cvt.u32.u64 %0, t; }"
        : "=r"(a) : "l"(p));
    return a;
}

__device__ __forceinline__ void tma_copy(float* dst, const float* src,
                                         uint32_t bytes, uint32_t mb) {
    asm volatile(
        "cp.async.bulk.shared::cluster.global.mbarrier::complete_tx::bytes "
        "[%0], [%1], %2, [%3];"
        :: "r"(smem_u32(dst)), "l"(src), "r"(bytes), "r"(mb) : "memory");
}

__device__ __forceinline__ void mbar_init1(uint32_t mb) {
    asm volatile("mbarrier.init.shared.b64 [%0], 1;" :: "r"(mb) : "memory");
}
__device__ __forceinline__ void mbar_expect(uint32_t mb, uint32_t bytes) {
    asm volatile("mbarrier.arrive.expect_tx.shared.b64 _, [%0], %1;"
                 :: "r"(mb), "r"(bytes) : "memory");
}

__device__ __forceinline__ void wait_tiles(int t, uint32_t mb) {
    if (t == 0) {
        uint32_t done = 0;
        while (!done) {
            asm volatile(
                "{ .reg .pred p; mbarrier.try_wait.parity.shared.b64 p, [%1], 0, 0x989680; "
                "selp.u32 %0, 1, 0, p; }"
                : "=r"(done) : "r"(mb) : "memory");
        }
    }
    __syncthreads();
}

// Gradient + bilinear gather (tm1-space). Returns hd; writes fdy.
__device__ __forceinline__ float grad_gather(const float* sm, const float* smc,
                                             int jj, int i0,
                                             bool interior_i, float rowsc,
                                             float fi, float& fdy_out) {
    float tcm = smc[jj];

    float dx;
    if (interior_i) {
        dx = 0.5f * (smc[jj + PADW] - smc[jj - PADW]);
    } else {
        float tcf = tcm + 1.0f;
        dx = 0.5f * (tcf * rowsc - tcf);
    }

    float dy;
    if (jj == 0) {
        float tcf = tcm + 1.0f;
        dy = 0.5f * (tcf * 1.1f - tcf);
    } else if (jj == Wd - 1) {
        float tcf = tcm + 1.0f;
        dy = 0.5f * (tcf * 0.9f - tcf);
    } else {
        dy = 0.5f * (smc[jj + 1] - smc[jj - 1]);
    }

    float rinv = rsqrtf(dx * dx + dy * dy + 1e-11f);
    float fdx = dx * rinv;
    float fdy = dy * rinv;
    fdy_out = fdy;

    float fx = (float)jj - fdx;
    float fy = fi - fdy;
    float x0 = floorf(fx), y0 = floorf(fy);
    float wx = fx - x0, wy = fy - y0;
    int ix = (int)x0;
    int iy = (int)y0;

    const float* g = sm + (iy - i0 + 2) * PADW + (ix + 4);
    float g00 = g[0];
    float g10 = g[1];
    float g01 = g[PADW];
    float g11 = g[PADW + 1];
    float nbm = (1.0f - wy) * ((1.0f - wx) * g00 + wx * g10)
              + wy          * ((1.0f - wx) * g01 + wx * g11);

    return tcm - nbm;
}

__device__ __forceinline__ float disp_fac(float fdy, int jj) {
    float ad = fabsf(fdy);
    float r2v = fmaxf(1.0f - ad, 0.0f);
    float fac = ad + r2v;
    if (jj == 0)        fac = fmaxf(-fdy, 0.0f) + r2v;  // t3 zeroed at col 0
    if (jj == Wd - 1)   fac = r2v + fmaxf(fdy, 0.0f);   // t1 zeroed at col W-1
    return fac;
}

// ---------------- fused steps 0+1, reading RAW input ----------------
// Stages raw input rows, transforms (1-x)*0.5-1 into padded tm1 layout in SMEM
// (g_padA never materialized). Step 0: dep==0 exactly -> same terrain for both
// steps -> one gradient/gather/fac; step-0 wat/vel stay in registers.
__global__ void __launch_bounds__(256)
step01_kernel(const float* __restrict__ input, float* __restrict__ pout,
              const float* __restrict__ rain0, const float* __restrict__ rain1) {
    __shared__ __align__(16) float smraw[(ROWS_PB + 4) * Wd];
    __shared__ __align__(16) float smp[(ROWS_PB + 4) * PADW];
    __shared__ __align__(16) float smr0[ROWS_PB * Wd];
    __shared__ __align__(16) float smr1[ROWS_PB * Wd];
    __shared__ __align__(8) unsigned long long mbar;

    int blk = blockIdx.x;
    int b = blk >> 7;
    int i0 = (blk & 127) << 2;
    int t = threadIdx.x;
    int r = t >> 6;
    int q = t & 63;
    int i = i0 + r;

    uint32_t mb = smem_u32(&mbar);
    // All TMA sources are pure harness inputs -> issue before pdl_wait.
    int lo = max(i0 - 2, 0);
    int hi = min(i0 + 5, Wd - 1);
    int nrows = hi - lo + 1;
    if (t == 0) {
        mbar_init1(mb);
        mbar_expect(mb, (uint32_t)(nrows * Wd * 4) + 2 * RAIN_BYTES);
        tma_copy(smraw + (lo - (i0 - 2)) * Wd,
                 input + (size_t)b * NPIX + (size_t)lo * Wd,
                 (uint32_t)(nrows * Wd * 4), mb);
        tma_copy(smr0, rain0 + (size_t)i0 * Wd, RAIN_BYTES, mb);
        tma_copy(smr1, rain1 + (size_t)i0 * Wd, RAIN_BYTES, mb);
    }
    pdl_wait();                 // init must have set g_par (read below) & padB borders
    wait_tiles(t, mb);

    // Transform raw -> padded tm1 layout, zero borders (matches padA semantics).
#pragma unroll
    for (int pr = 0; pr < ROWS_PB + 4; ++pr) {
        int L = i0 - 2 + pr;
        bool rowok = (L >= 0) && (L <= Wd - 1);
        for (int c = t; c < PADW; c += 256) {
            float v = 0.0f;
            if (rowok && c >= 4 && c < 4 + Wd) {
                float x = smraw[pr * Wd + (c - 4)];
                float t0v = (1.0f - x) * 0.5f;
                v = t0v - 1.0f;
            }
            smp[pr * PADW + c] = v;
        }
    }
    __syncthreads();

    const float4* parv = reinterpret_cast<const float4*>(g_par);
    float4 pA = parv[0];  // x=rain_rate' y=heps z=minhd w=kc'
    float4 pB = parv[1];  // x=dis y=dep z=evap' w=grav'

    const float* smc = smp + (r + 2) * PADW + 4;
    const float* smrr0 = smr0 + r * Wd;
    const float* smrr1 = smr1 + r * Wd;
    bool interior_i = (i > 0) && (i < Wd - 1);
    float rowsc = (i == 0) ? 1.1f : 0.9f;
    float fi = (float)i;
    int cbase = b * NPIX + i * Wd;
    float* porow = pout + (size_t)b * PADN + (size_t)(i + 2) * PADW + 4;

#pragma unroll
    for (int k = 0; k < 8; ++k) {
        int jj = q + (k << 6);

        float fdy;
        float hd = grad_gather(smp, smc, jj, i0, interior_i, rowsc, fi, fdy);
        float fac = disp_fac(fdy, jj);

        // --- step 0 (register-resident; dep==0 exact) ---
        float w0 = pA.x * smrr0[jj];
        float wat0 = (fac * w0) * pB.z;
        float vel0 = pB.w * hd;

        // --- step 1 (s == 0 folds, exact) ---
        float nhd = (hd > pA.y) ? fmaxf(hd, pA.z) : 0.0f;
        float w = wat0 + pA.x * smrr1[jj];
        float scap = nhd * pA.w * vel0 * w;
        float sdiff = 0.0f - scap;
        float third = (hd < 0.0f) ? 0.0f
                    : (fmaxf(sdiff * pB.y, 0.0f) - fmaxf(-sdiff * pB.x, 0.0f));
        float dep = fmaxf(-fmaxf(hd, 0.0f), 0.0f + third);

        float s2 = 0.0f - dep;
        float t2m = smc[jj] + dep;

        int cidx = cbase + jj;
        g_sw[cidx] = make_float2(fac * s2, (fac * w) * pB.z);
        g_vel[cidx] = pB.w * hd;
        porow[jj] = t2m;
    }
    pdl_launch_dependents();
}

// ---------------- generic step ----------------
template <bool LAST>
__global__ void __launch_bounds__(256)
step_kernel(const float* __restrict__ pin, float* __restrict__ pout,
            const float* __restrict__ rain, float* __restrict__ outp) {
    __shared__ __align__(16) float sm[(ROWS_PB + 4) * PADW];
    __shared__ __align__(16) float smr[ROWS_PB * Wd];
    __shared__ __align__(8) unsigned long long mbar;

    int blk = blockIdx.x;
    int b = blk >> 7;
    int i0 = (blk & 127) << 2;
    int t = threadIdx.x;
    int r = t >> 6;
    int q = t & 63;
    int i = i0 + r;

    uint32_t mb = smem_u32(&mbar);
    // rain is a pure input -> TMA before pdl_wait; terrain depends on predecessor.
    if (t == 0) {
        mbar_init1(mb);
        mbar_expect(mb, FILL_BYTES + RAIN_BYTES);
        tma_copy(smr, rain + (size_t)i0 * Wd, RAIN_BYTES, mb);
    }
    pdl_wait();
    if (t == 0) {
        tma_copy(sm, pin + (size_t)b * PADN + (size_t)i0 * PADW, FILL_BYTES, mb);
    }

    int cbase = b * NPIX + i * Wd;

    const float4* parv = reinterpret_cast<const float4*>(g_par);
    float4 pA = parv[0];  // x=rain_rate' y=heps z=minhd w=kc'
    float4 pB = parv[1];  // x=dis y=dep z=evap' w=grav'

    // ---- first half's state loads, front-batched to overlap the TMA fills ----
    float2 sw_[4];
    float v_[4];
#pragma unroll
    for (int k = 0; k < 4; ++k) {
        int jj = q + (k << 6);
        sw_[k] = g_sw[cbase + jj];
        v_[k]  = g_vel[cbase + jj];
    }

    wait_tiles(t, mb);

    const float* smc = sm + (r + 2) * PADW + 4;
    const float* smrr = smr + r * Wd;
    bool interior_i = (i > 0) && (i < Wd - 1);
    float rowsc = (i == 0) ? 1.1f : 0.9f;
    float fi = (float)i;
    float* porow = pout + (size_t)b * PADN + (size_t)(i + 2) * PADW + 4;

#pragma unroll
    for (int half = 0; half < 2; ++half) {
        if (half == 1) {
#pragma unroll
            for (int k = 0; k < 4; ++k) {
                int jj = q + ((k + 4) << 6);
                sw_[k] = g_sw[cbase + jj];
                v_[k]  = g_vel[cbase + jj];
            }
        }

#pragma unroll
        for (int k = 0; k < 4; ++k) {
            int jj = q + ((half * 4 + k) << 6);

            float fdy;
            float hd = grad_gather(sm, smc, jj, i0, interior_i, rowsc, fi, fdy);
            float nhd = (hd > pA.y) ? fmaxf(hd, pA.z) : 0.0f;

            float s = sw_[k].x;
            float w = sw_[k].y + pA.x * smrr[jj];

            float scap = nhd * pA.w * v_[k] * w;
            float first = fminf(fmaxf(-hd, 0.0f), s);
            float sdiff = s - scap;
            float third = (hd < 0.0f) ? 0.0f
                        : (fmaxf(sdiff * pB.y, 0.0f) - fmaxf(-sdiff * pB.x, 0.0f));
            float dep = fmaxf(-fmaxf(hd, 0.0f), first + third);

            float t2m = smc[jj] + dep;    // = new terrain - 1

            if (LAST) {
                // Post-step-9 state dead: no displacement, no state stores.
                outp[cbase + jj] = fmaxf(-2.0f * t2m, 0.0f) - 1.0f;
            } else {
                float s2 = s - dep;
                float fac = disp_fac(fdy, jj);
                int cidx = cbase + jj;
                g_sw[cidx] = make_float2(fac * s2, (fac * w) * pB.z);
                g_vel[cidx] = pB.w * hd;
                porow[jj] = t2m;
            }
        }
    }
    pdl_launch_dependents();
}

template <typename F, typename... Args>
static inline void launch_pdl(F fn, dim3 g, dim3 b, Args... args) {
    cudaLaunchConfig_t cfg = {};
    cfg.gridDim = g;
    cfg.blockDim = b;
    cfg.dynamicSmemBytes = 0;
    cfg.stream = 0;
    cudaLaunchAttribute at[1];
    at[0].id = cudaLaunchAttributeProgrammaticStreamSerialization;
    at[0].val.programmaticStreamSerializationAllowed = 1;
    cfg.attrs = at;
    cfg.numAttrs = 1;
    cudaLaunchKernelEx(&cfg, fn, args...);
}

extern "C" void kernel_launch(void* const* d_in, const int* in_sizes, int n_in,
                              void* d_out, int out_size) {
    const float* input     = (const float*)d_in[0];
    const float* rainall   = (const float*)d_in[1];
    // d_in[2] (random_gradient) provably unused: factor == relu(1e-10 - mag) == 0 in fp32.
    const float* rain_rate = (const float*)d_in[3];
    const float* evap      = (const float*)d_in[4];
    const float* minhd     = (const float*)d_in[5];
    const float* heps      = (const float*)d_in[6];
    const float* grav      = (const float*)d_in[7];
    const float* kc        = (const float*)d_in[8];
    const float* dis       = (const float*)d_in[9];
    const float* depr      = (const float*)d_in[10];
    float* out = (float*)d_out;

    float *pA, *pB;
    cudaGetSymbolAddress((void**)&pA, g_padA);
    cudaGetSymbolAddress((void**)&pB, g_padB);

    init_kernel<<<BATCH * PADH, PADW>>>(rain_rate, evap, minhd, heps,
                                        grav, kc, dis, depr);

    // Fused steps 0+1, reading raw input (padA's interior never materialized).
    launch_pdl(step01_kernel, dim3(BATCH * 128), dim3(256),
               input, pB, rainall, rainall + (size_t)NPIX);

    // Steps 2..9: ping-pong terrain (step 2 reads pB).
    for (int it = 2; it < 10; ++it) {
        const float* pin = (it & 1) ? pA : pB;
        float* pout      = (it & 1) ? pB : pA;
        const float* rain = rainall + (size_t)it * NPIX;
        if (it == 9) {
            launch_pdl(step_kernel<true>, dim3(BATCH * 128), dim3(256),
                       pin, pout, rain, out);
        } else {
            launch_pdl(step_kernel<false>, dim3(BATCH * 128), dim3(256),
                       pin, pout, rain, out);
        }
    }
}